// round 14
// baseline (speedup 1.0000x reference)
#include <cuda_runtime.h>
#include <cstdint>

// ============================================================================
// CausalAttentionHead: B=8, S=2048, E=768, H=128, fp32.
//   Kernel 1: masked QKV projection (R11 winner, unchanged).
//   Kernel 2: flash attention, R11 geometry (256 thr, 4q x 4k) + unroll-4 hot
//             loops + duplicated-pair P store (no pack MOVs in PV).
// Packed fma.rn.f32x2 (Blackwell) = 2 fp32 MAC/inst on the FMA pipe.
// NOTE: tcgen05 unusable (harness PTX target compute_103, no 'a').
//       512-thr partition (R13) is crossbar-bound: 4q x 4k @256 is optimal.
// ============================================================================

#define NB 8
#define NS 2048
#define NE 768
#define NH 128
#define MROWS (NB * NS)

typedef unsigned long long u64;
#define DEV_INLINE __device__ __forceinline__

struct alignas(16) U64x2 { u64 lo, hi; };   // ld.shared.v2.u64 vehicle

// -------------------- packed f32x2 helpers --------------------
DEV_INLINE u64 ffma2(u64 a, u64 b, u64 c) {
    u64 d;
    asm("fma.rn.f32x2 %0, %1, %2, %3;" : "=l"(d) : "l"(a), "l"(b), "l"(c));
    return d;
}
DEV_INLINE u64 fmul2(u64 a, u64 b) {
    u64 d;
    asm("mul.rn.f32x2 %0, %1, %2;" : "=l"(d) : "l"(a), "l"(b));
    return d;
}
DEV_INLINE u64 pack2(float lo, float hi) {
    u64 r;
    asm("mov.b64 %0, {%1, %2};" : "=l"(r) : "f"(lo), "f"(hi));
    return r;
}
DEV_INLINE float2 unpack2(u64 v) {
    float2 f;
    asm("mov.b64 {%0, %1}, %2;" : "=f"(f.x), "=f"(f.y) : "l"(v));
    return f;
}

// -------------------- cp.async helpers (16B, L2-direct) --------------------
DEV_INLINE void cp16(void* smem, const void* g) {
    unsigned sa = (unsigned)__cvta_generic_to_shared(smem);
    asm volatile("cp.async.cg.shared.global [%0], [%1], 16;"
                 :: "r"(sa), "l"(g) : "memory");
}
DEV_INLINE void cp_commit() { asm volatile("cp.async.commit_group;" ::: "memory"); }
template <int N>
DEV_INLINE void cp_wait() { asm volatile("cp.async.wait_group %0;" :: "n"(N) : "memory"); }

// FMA-pipe 2^t, clamped to [-125, 60]. deg-6 poly on [0,1): rel err ~1e-5.
DEV_INLINE float fast_exp2(float t) {
    t = fminf(fmaxf(t, -125.0f), 60.0f);
    float n = floorf(t);
    float f = t - n;
    float p = 1.5403530393381606e-4f;
    p = fmaf(p, f, 1.3333558146428443e-3f);
    p = fmaf(p, f, 9.6181291076284770e-3f);
    p = fmaf(p, f, 5.5504108664821580e-2f);
    p = fmaf(p, f, 2.4022650695910070e-1f);
    p = fmaf(p, f, 6.9314718055994530e-1f);
    p = fmaf(p, f, 1.0f);
    return __int_as_float(((int)n + 127) << 23) * p;
}

// -------------------- scratch (no allocation allowed) --------------------
__device__ float g_q[MROWS * NH];
__device__ float g_k[MROWS * NH];
__device__ float g_v[MROWS * NH];

// ============================================================================
// Kernel 1: QKV projection (R11 winner, unchanged). 256 threads, BM=128,
// BN=128, BK=32, 8x8 tile, interleaved rows, one barrier per k-chunk.
// ============================================================================
#define QX_S 36
#define QKV_STAGE (128 * QX_S * 2)
#define QKV_SMEM_BYTES (2 * QKV_STAGE * 4)

__global__ __launch_bounds__(256, 1)
void qkv_kernel(const float* __restrict__ X, const float* __restrict__ pm,
                const float* __restrict__ Wq, const float* __restrict__ Wk,
                const float* __restrict__ Wv) {
    extern __shared__ float smf[];

    const int tid  = threadIdx.x;
    const int row0 = blockIdx.x * 128;
    const int z    = blockIdx.y;
    const float* W = (z == 0) ? Wq : (z == 1) ? Wk : Wv;
    float* dst     = (z == 0) ? g_q : (z == 1) ? g_k : g_v;

    const int rg = tid >> 4;   // rows rg + 16*i
    const int cg = tid & 15;   // cols cg + 16*j

    const int fc = (tid & 7) << 2;
    const int fr = tid >> 3;
    const float* xr[4]; const float* wr[4];
#pragma unroll
    for (int t = 0; t < 4; t++) {
        int r = fr + t * 32;
        xr[t] = X + (u64)(row0 + r) * NE + fc;
        wr[t] = W + (u64)r * NE + fc;
    }
    const int soff = fr * QX_S + fc;

    u64 acc[8][8];
#pragma unroll
    for (int i = 0; i < 8; i++)
#pragma unroll
        for (int j = 0; j < 8; j++) acc[i][j] = 0ULL;

    {
        float* sX = smf;
        float* sW = smf + 128 * QX_S;
#pragma unroll
        for (int t = 0; t < 4; t++) {
            cp16(sX + soff + t * 32 * QX_S, xr[t]);
            cp16(sW + soff + t * 32 * QX_S, wr[t]);
        }
        cp_commit();
    }

    for (int kc = 0; kc < 24; kc++) {
        const int cur = kc & 1;
        cp_wait<0>();
        __syncthreads();
        if (kc < 23) {
            float* sX = smf + (cur ^ 1) * QKV_STAGE;
            float* sW = sX + 128 * QX_S;
            const int k1 = (kc + 1) * 32;
#pragma unroll
            for (int t = 0; t < 4; t++) {
                cp16(sX + soff + t * 32 * QX_S, xr[t] + k1);
                cp16(sW + soff + t * 32 * QX_S, wr[t] + k1);
            }
            cp_commit();
        }

        const float* sX = smf + cur * QKV_STAGE;
        const float* sW = sX + 128 * QX_S;
#pragma unroll
        for (int kp2 = 0; kp2 < 8; kp2++) {
            U64x2 a4[8];
#pragma unroll
            for (int i = 0; i < 8; i++)
                a4[i] = *(const U64x2*)(sX + (rg + 16 * i) * QX_S + 4 * kp2);
#pragma unroll
            for (int j = 0; j < 8; j++) {
                U64x2 b4 = *(const U64x2*)(sW + (cg + 16 * j) * QX_S + 4 * kp2);
#pragma unroll
                for (int i = 0; i < 8; i++) {
                    acc[i][j] = ffma2(a4[i].lo, b4.lo, acc[i][j]);
                    acc[i][j] = ffma2(a4[i].hi, b4.hi, acc[i][j]);
                }
            }
        }
    }

    const float scale = (z == 0) ? (0.08838834764831845f * 1.4426950408889634f) : 1.0f;
#pragma unroll
    for (int i = 0; i < 8; i++) {
        int gr = row0 + rg + 16 * i;
        float mrow = pm[gr] * scale;
#pragma unroll
        for (int j = 0; j < 8; j++) {
            float2 f = unpack2(acc[i][j]);
            dst[(u64)gr * NH + cg + 16 * j] = (f.x + f.y) * mrow;
        }
    }
}

// ============================================================================
// Kernel 2: flash attention. Grid (16,8): CTA x does q-tiles (31-x) then (x)
// -> exactly 33 kb-iterations. BM=BN=64, D=128, 256 thr (4q x 4k per thread).
// Duplicated-pair P store: softmax writes (p,p) float2, PV loads ready-packed
// u64 coefficients (zero pack MOVs). Unroll-4 hot loops for LDS latency cover.
// ============================================================================
#define SQ_S 132   // group pair 1 row apart == 4 banks: conflict-free
#define SK_S 132
#define SV_S 128
#define SS_S 136   // duplicated pairs: 64 keys * 2 floats, 16B-aligned rows
#define KV_STAGE (64 * (SK_S + SV_S))
#define ATTN_SMEM_FLOATS (64 * SQ_S + 2 * KV_STAGE + 64 * SS_S)
#define ATTN_SMEM_BYTES  (ATTN_SMEM_FLOATS * 4)

__global__ __launch_bounds__(256, 1)
void attn_kernel(float* __restrict__ out) {
    extern __shared__ float smf[];
    float* sQ   = smf;
    float* sKV0 = sQ + 64 * SQ_S;            // [sK | sV] stage 0
    float* sKV1 = sKV0 + KV_STAGE;           // [sK | sV] stage 1
    float* sS   = sKV1 + KV_STAGE;           // (p,p) pairs

    const int tid  = threadIdx.x;
    const int qgs  = tid >> 4;   // 0..15: rows qgs + 16*i (group-exclusive set)
    const int kgs  = tid & 15;   // score: keys kgs+16j ; PV: d-chunks 4*kgs(+64)
    const int b    = blockIdx.y;
    const int base = b << 11;    // b * 2048

    const int flr = tid >> 5;
    const int flc = (tid & 31) << 2;

#pragma unroll 1
    for (int pass = 0; pass < 2; pass++) {
        const int qt = pass == 0 ? (31 - blockIdx.x) : blockIdx.x;
        const int q0 = qt * 64;

        __syncthreads();   // prior pass readers of sQ / stage buffers done
        {
            const float* qptr = g_q + (u64)(base + q0) * NH;
            const float* kptr = g_k + (u64)base * NH;
            const float* vptr = g_v + (u64)base * NH;
#pragma unroll
            for (int t = 0; t < 8; t++) {
                int r = flr + t * 8;
                cp16(sQ + r * SQ_S + flc, qptr + r * NH + flc);
                cp16(sKV0 + r * SK_S + flc, kptr + r * NH + flc);
                cp16(sKV0 + 64 * SK_S + r * SV_S + flc, vptr + r * NH + flc);
            }
            cp_commit();
        }

        float lp[4];
#pragma unroll
        for (int i = 0; i < 4; i++) lp[i] = 0.0f;
        u64 accO[4][4];   // [i][0..1]=floats 4kgs..+3, [i][2..3]=floats 4kgs+64..+67
#pragma unroll
        for (int i = 0; i < 4; i++)
#pragma unroll
            for (int j = 0; j < 4; j++) accO[i][j] = 0ULL;

        for (int kb = 0; kb <= qt; kb++) {
            const int cur = kb & 1;
            cp_wait<0>();               // own stage-cur (and Q) copies done
            __syncthreads();            // publish; readers of cur^1 done
            if (kb < qt) {              // prefetch kb+1 into cur^1, overlaps below
                float* dstKV = (cur == 0) ? sKV1 : sKV0;
                const float* kptr = g_k + (u64)(base + (kb + 1) * 64) * NH;
                const float* vptr = g_v + (u64)(base + (kb + 1) * 64) * NH;
#pragma unroll
                for (int t = 0; t < 8; t++) {
                    int r = flr + t * 8;
                    cp16(dstKV + r * SK_S + flc, kptr + r * NH + flc);
                    cp16(dstKV + 64 * SK_S + r * SV_S + flc, vptr + r * NH + flc);
                }
                cp_commit();
            }

            const float* sK = (cur == 0) ? sKV0 : sKV1;
            const float* sV = sK + 64 * SK_S;

            // ---- scores: 4q x 4k per thread, LDS.128 over d, unroll 4 ----
            u64 accS[4][4];
#pragma unroll
            for (int i = 0; i < 4; i++)
#pragma unroll
                for (int j = 0; j < 4; j++) accS[i][j] = 0ULL;
#pragma unroll 4
            for (int dp2 = 0; dp2 < 32; dp2++) {       // 4 d-floats per iter
                U64x2 a4[4];
#pragma unroll
                for (int i = 0; i < 4; i++)
                    a4[i] = *(const U64x2*)(sQ + (qgs + 16 * i) * SQ_S + 4 * dp2);
#pragma unroll
                for (int j = 0; j < 4; j++) {
                    U64x2 k4 = *(const U64x2*)(sK + (kgs + 16 * j) * SK_S + 4 * dp2);
#pragma unroll
                    for (int i = 0; i < 4; i++) {
                        accS[i][j] = ffma2(a4[i].lo, k4.lo, accS[i][j]);
                        accS[i][j] = ffma2(a4[i].hi, k4.hi, accS[i][j]);
                    }
                }
            }
            float s[4][4];
#pragma unroll
            for (int i = 0; i < 4; i++)
#pragma unroll
                for (int j = 0; j < 4; j++) {
                    float2 f = unpack2(accS[i][j]);
                    s[i][j] = f.x + f.y;
                }
            if (kb == qt) {   // diagonal block: per-element causal mask
#pragma unroll
                for (int i = 0; i < 4; i++)
#pragma unroll
                    for (int j = 0; j < 4; j++)
                        if (kgs + 16 * j > qgs + 16 * i) s[i][j] = -1.0e30f;
            }

            // ---- fixed-max softmax: write (p,p) pairs; partial l in regs ----
#pragma unroll
            for (int i = 0; i < 4; i++) {
                const int row = qgs + 16 * i;
#pragma unroll
                for (int j = 0; j < 4; j++) {
                    float p = fast_exp2(s[i][j]);
                    *(float2*)(sS + row * SS_S + 2 * (kgs + 16 * j)) = make_float2(p, p);
                    lp[i] += p;
                }
            }
            __syncwarp();   // sS written/read within the same 16-lane groups only

            // ---- PV: ready-packed p (u64 dup-pairs), v via LDS.128, unroll 4 ----
#pragma unroll 4
            for (int kj4 = 0; kj4 < 16; kj4++) {
                U64x2 pa[4], pb[4];   // pa: kj,kj+1 ; pb: kj+2,kj+3 (each (p,p))
#pragma unroll
                for (int i = 0; i < 4; i++) {
                    const float* pr = sS + (qgs + 16 * i) * SS_S + 8 * kj4;
                    pa[i] = *(const U64x2*)pr;
                    pb[i] = *(const U64x2*)(pr + 4);
                }
#pragma unroll
                for (int t = 0; t < 4; t++) {
                    const int kj = 4 * kj4 + t;
                    U64x2 va = *(const U64x2*)(sV + kj * SV_S + 4 * kgs);
                    U64x2 vb = *(const U64x2*)(sV + kj * SV_S + 4 * kgs + 64);
#pragma unroll
                    for (int i = 0; i < 4; i++) {
                        u64 p2 = (t == 0) ? pa[i].lo : (t == 1) ? pa[i].hi
                               : (t == 2) ? pb[i].lo : pb[i].hi;
                        accO[i][0] = ffma2(p2, va.lo, accO[i][0]);
                        accO[i][1] = ffma2(p2, va.hi, accO[i][1]);
                        accO[i][2] = ffma2(p2, vb.lo, accO[i][2]);
                        accO[i][3] = ffma2(p2, vb.hi, accO[i][3]);
                    }
                }
            }
        }

        // ---- finalize: reduce l across the 16-lane group once, divide, write ----
#pragma unroll
        for (int i = 0; i < 4; i++) {
            float rs = lp[i];
#pragma unroll
            for (int off = 8; off >= 1; off >>= 1)
                rs += __shfl_xor_sync(0xffffffffu, rs, off);
            float inv = 1.0f / rs;
            u64 inv2 = pack2(inv, inv);
            float* optr = out + (u64)(base + q0 + qgs + 16 * i) * NH;
            *(u64*)(optr + 4 * kgs)      = fmul2(accO[i][0], inv2);
            *(u64*)(optr + 4 * kgs + 2)  = fmul2(accO[i][1], inv2);
            *(u64*)(optr + 4 * kgs + 64) = fmul2(accO[i][2], inv2);
            *(u64*)(optr + 4 * kgs + 66) = fmul2(accO[i][3], inv2);
        }
    }
}

// ============================================================================
extern "C" void kernel_launch(void* const* d_in, const int* in_sizes, int n_in,
                              void* d_out, int out_size) {
    const float* X  = (const float*)d_in[0];
    const float* pm = (const float*)d_in[1];
    const float* Wq = (const float*)d_in[2];
    const float* Wk = (const float*)d_in[3];
    const float* Wv = (const float*)d_in[4];
    float* out = (float*)d_out;

    static bool attr_set = false;   // host-side config, identical every call
    if (!attr_set) {
        cudaFuncSetAttribute(qkv_kernel, cudaFuncAttributeMaxDynamicSharedMemorySize,
                             QKV_SMEM_BYTES);
        cudaFuncSetAttribute(attn_kernel, cudaFuncAttributeMaxDynamicSharedMemorySize,
                             ATTN_SMEM_BYTES);
        attr_set = true;
    }

    qkv_kernel<<<dim3(MROWS / 128, 3, 1), 256, QKV_SMEM_BYTES>>>(X, pm, Wq, Wk, Wv);
    attn_kernel<<<dim3(16, 8, 1), 256, ATTN_SMEM_BYTES>>>(out);
}

// round 16
// speedup vs baseline: 1.7132x; 1.7132x over previous
#include <cuda_runtime.h>
#include <cstdint>

// ============================================================================
// CausalAttentionHead: B=8, S=2048, E=768, H=128, fp32.
//   Kernel 1: masked QKV projection (R11 winner, unchanged).
//   Kernel 2: flash attention, R11 inner loops byte-identical; schedule changed
//             to ONE q-tile per CTA, grid=256 (>=148: avoids the low-grid
//             issue throttle for >32KB bodies), weight-descending dispatch.
// Packed fma.rn.f32x2 (Blackwell) = 2 fp32 MAC/inst on the FMA pipe.
// NOTES (locked-in negative results):
//   - tcgen05 unusable: harness PTX targets compute_103 (no 'a').
//   - 512-thr 2qx4k partition is crossbar-bound (R13); 4qx4k@256 is optimal.
//   - unroll-4 / fatter bodies trip the body>32KB low-grid throttle (R14).
// ============================================================================

#define NB 8
#define NS 2048
#define NE 768
#define NH 128
#define MROWS (NB * NS)

typedef unsigned long long u64;
#define DEV_INLINE __device__ __forceinline__

struct alignas(16) U64x2 { u64 lo, hi; };   // ld.shared.v2.u64 vehicle

// -------------------- packed f32x2 helpers --------------------
DEV_INLINE u64 ffma2(u64 a, u64 b, u64 c) {
    u64 d;
    asm("fma.rn.f32x2 %0, %1, %2, %3;" : "=l"(d) : "l"(a), "l"(b), "l"(c));
    return d;
}
DEV_INLINE u64 fmul2(u64 a, u64 b) {
    u64 d;
    asm("mul.rn.f32x2 %0, %1, %2;" : "=l"(d) : "l"(a), "l"(b));
    return d;
}
DEV_INLINE u64 pack2(float lo, float hi) {
    u64 r;
    asm("mov.b64 %0, {%1, %2};" : "=l"(r) : "f"(lo), "f"(hi));
    return r;
}
DEV_INLINE float2 unpack2(u64 v) {
    float2 f;
    asm("mov.b64 {%0, %1}, %2;" : "=f"(f.x), "=f"(f.y) : "l"(v));
    return f;
}

// -------------------- cp.async helpers (16B, L2-direct) --------------------
DEV_INLINE void cp16(void* smem, const void* g) {
    unsigned sa = (unsigned)__cvta_generic_to_shared(smem);
    asm volatile("cp.async.cg.shared.global [%0], [%1], 16;"
                 :: "r"(sa), "l"(g) : "memory");
}
DEV_INLINE void cp_commit() { asm volatile("cp.async.commit_group;" ::: "memory"); }
template <int N>
DEV_INLINE void cp_wait() { asm volatile("cp.async.wait_group %0;" :: "n"(N) : "memory"); }

// FMA-pipe 2^t, clamped to [-125, 60]. deg-6 poly on [0,1): rel err ~1e-5.
DEV_INLINE float fast_exp2(float t) {
    t = fminf(fmaxf(t, -125.0f), 60.0f);
    float n = floorf(t);
    float f = t - n;
    float p = 1.5403530393381606e-4f;
    p = fmaf(p, f, 1.3333558146428443e-3f);
    p = fmaf(p, f, 9.6181291076284770e-3f);
    p = fmaf(p, f, 5.5504108664821580e-2f);
    p = fmaf(p, f, 2.4022650695910070e-1f);
    p = fmaf(p, f, 6.9314718055994530e-1f);
    p = fmaf(p, f, 1.0f);
    return __int_as_float(((int)n + 127) << 23) * p;
}

// -------------------- scratch (no allocation allowed) --------------------
__device__ float g_q[MROWS * NH];
__device__ float g_k[MROWS * NH];
__device__ float g_v[MROWS * NH];

// ============================================================================
// Kernel 1: QKV projection (R11 winner, unchanged). 256 threads, BM=128,
// BN=128, BK=32, 8x8 tile, interleaved rows, one barrier per k-chunk.
// ============================================================================
#define QX_S 36
#define QKV_STAGE (128 * QX_S * 2)
#define QKV_SMEM_BYTES (2 * QKV_STAGE * 4)

__global__ __launch_bounds__(256, 1)
void qkv_kernel(const float* __restrict__ X, const float* __restrict__ pm,
                const float* __restrict__ Wq, const float* __restrict__ Wk,
                const float* __restrict__ Wv) {
    extern __shared__ float smf[];

    const int tid  = threadIdx.x;
    const int row0 = blockIdx.x * 128;
    const int z    = blockIdx.y;
    const float* W = (z == 0) ? Wq : (z == 1) ? Wk : Wv;
    float* dst     = (z == 0) ? g_q : (z == 1) ? g_k : g_v;

    const int rg = tid >> 4;   // rows rg + 16*i
    const int cg = tid & 15;   // cols cg + 16*j

    const int fc = (tid & 7) << 2;
    const int fr = tid >> 3;
    const float* xr[4]; const float* wr[4];
#pragma unroll
    for (int t = 0; t < 4; t++) {
        int r = fr + t * 32;
        xr[t] = X + (u64)(row0 + r) * NE + fc;
        wr[t] = W + (u64)r * NE + fc;
    }
    const int soff = fr * QX_S + fc;

    u64 acc[8][8];
#pragma unroll
    for (int i = 0; i < 8; i++)
#pragma unroll
        for (int j = 0; j < 8; j++) acc[i][j] = 0ULL;

    {
        float* sX = smf;
        float* sW = smf + 128 * QX_S;
#pragma unroll
        for (int t = 0; t < 4; t++) {
            cp16(sX + soff + t * 32 * QX_S, xr[t]);
            cp16(sW + soff + t * 32 * QX_S, wr[t]);
        }
        cp_commit();
    }

    for (int kc = 0; kc < 24; kc++) {
        const int cur = kc & 1;
        cp_wait<0>();
        __syncthreads();
        if (kc < 23) {
            float* sX = smf + (cur ^ 1) * QKV_STAGE;
            float* sW = sX + 128 * QX_S;
            const int k1 = (kc + 1) * 32;
#pragma unroll
            for (int t = 0; t < 4; t++) {
                cp16(sX + soff + t * 32 * QX_S, xr[t] + k1);
                cp16(sW + soff + t * 32 * QX_S, wr[t] + k1);
            }
            cp_commit();
        }

        const float* sX = smf + cur * QKV_STAGE;
        const float* sW = sX + 128 * QX_S;
#pragma unroll
        for (int kp2 = 0; kp2 < 8; kp2++) {
            U64x2 a4[8];
#pragma unroll
            for (int i = 0; i < 8; i++)
                a4[i] = *(const U64x2*)(sX + (rg + 16 * i) * QX_S + 4 * kp2);
#pragma unroll
            for (int j = 0; j < 8; j++) {
                U64x2 b4 = *(const U64x2*)(sW + (cg + 16 * j) * QX_S + 4 * kp2);
#pragma unroll
                for (int i = 0; i < 8; i++) {
                    acc[i][j] = ffma2(a4[i].lo, b4.lo, acc[i][j]);
                    acc[i][j] = ffma2(a4[i].hi, b4.hi, acc[i][j]);
                }
            }
        }
    }

    const float scale = (z == 0) ? (0.08838834764831845f * 1.4426950408889634f) : 1.0f;
#pragma unroll
    for (int i = 0; i < 8; i++) {
        int gr = row0 + rg + 16 * i;
        float mrow = pm[gr] * scale;
#pragma unroll
        for (int j = 0; j < 8; j++) {
            float2 f = unpack2(acc[i][j]);
            dst[(u64)gr * NH + cg + 16 * j] = (f.x + f.y) * mrow;
        }
    }
}

// ============================================================================
// Kernel 2: flash attention. Grid 256 linear; bid -> qt = 31 - (bid>>3),
// b = bid&7 (strict weight-descending dispatch -> greedy LPT over 2 waves).
// BM=BN=64, D=128, 256 thr (4q x 4k per thread). Inner loops = R11 winner.
// ============================================================================
#define SQ_S 132   // group pair 1 row apart == 4 banks: conflict-free
#define SK_S 132
#define SV_S 128
#define SS_S 68
#define KV_STAGE (64 * (SK_S + SV_S))
#define ATTN_SMEM_FLOATS (64 * SQ_S + 2 * KV_STAGE + 64 * SS_S)
#define ATTN_SMEM_BYTES  (ATTN_SMEM_FLOATS * 4)

__global__ __launch_bounds__(256, 1)
void attn_kernel(float* __restrict__ out) {
    extern __shared__ float smf[];
    float* sQ   = smf;
    float* sKV0 = sQ + 64 * SQ_S;            // [sK | sV] stage 0
    float* sKV1 = sKV0 + KV_STAGE;           // [sK | sV] stage 1
    float* sS   = sKV1 + KV_STAGE;

    const int tid  = threadIdx.x;
    const int qgs  = tid >> 4;   // 0..15: rows qgs + 16*i (group-exclusive set)
    const int kgs  = tid & 15;   // score: keys kgs+16j ; PV: d-chunks 4*kgs(+64)
    const int bid  = blockIdx.x;
    const int qt   = 31 - (bid >> 3);   // heavy tiles dispatched first
    const int b    = bid & 7;
    const int q0   = qt * 64;
    const int base = b << 11;    // b * 2048

    const int flr = tid >> 5;
    const int flc = (tid & 31) << 2;

    // prologue: Q tile + K/V block 0, one cp.async group
    {
        const float* qptr = g_q + (u64)(base + q0) * NH;
        const float* kptr = g_k + (u64)base * NH;
        const float* vptr = g_v + (u64)base * NH;
#pragma unroll
        for (int t = 0; t < 8; t++) {
            int r = flr + t * 8;
            cp16(sQ + r * SQ_S + flc, qptr + r * NH + flc);
            cp16(sKV0 + r * SK_S + flc, kptr + r * NH + flc);
            cp16(sKV0 + 64 * SK_S + r * SV_S + flc, vptr + r * NH + flc);
        }
        cp_commit();
    }

    float lp[4];                 // per-thread partial row sums
#pragma unroll
    for (int i = 0; i < 4; i++) lp[i] = 0.0f;
    u64 accO[4][4];   // [i][0..1]=floats 4kgs..+3, [i][2..3]=floats 4kgs+64..+67
#pragma unroll
    for (int i = 0; i < 4; i++)
#pragma unroll
        for (int j = 0; j < 4; j++) accO[i][j] = 0ULL;

    for (int kb = 0; kb <= qt; kb++) {
        const int cur = kb & 1;
        cp_wait<0>();               // own stage-cur (and Q) copies done
        __syncthreads();            // publish; readers of cur^1 done
        if (kb < qt) {              // prefetch kb+1 into cur^1, overlaps below
            float* dstKV = (cur == 0) ? sKV1 : sKV0;
            const float* kptr = g_k + (u64)(base + (kb + 1) * 64) * NH;
            const float* vptr = g_v + (u64)(base + (kb + 1) * 64) * NH;
#pragma unroll
            for (int t = 0; t < 8; t++) {
                int r = flr + t * 8;
                cp16(dstKV + r * SK_S + flc, kptr + r * NH + flc);
                cp16(dstKV + 64 * SK_S + r * SV_S + flc, vptr + r * NH + flc);
            }
            cp_commit();
        }

        const float* sK = (cur == 0) ? sKV0 : sKV1;
        const float* sV = sK + 64 * SK_S;

        // ---- scores: 4q x 4k per thread, LDS.128 over d ----
        u64 accS[4][4];
#pragma unroll
        for (int i = 0; i < 4; i++)
#pragma unroll
            for (int j = 0; j < 4; j++) accS[i][j] = 0ULL;
#pragma unroll 2
        for (int dp2 = 0; dp2 < 32; dp2++) {       // 4 d-floats per iter
            U64x2 a4[4];
#pragma unroll
            for (int i = 0; i < 4; i++)
                a4[i] = *(const U64x2*)(sQ + (qgs + 16 * i) * SQ_S + 4 * dp2);
#pragma unroll
            for (int j = 0; j < 4; j++) {
                U64x2 k4 = *(const U64x2*)(sK + (kgs + 16 * j) * SK_S + 4 * dp2);
#pragma unroll
                for (int i = 0; i < 4; i++) {
                    accS[i][j] = ffma2(a4[i].lo, k4.lo, accS[i][j]);
                    accS[i][j] = ffma2(a4[i].hi, k4.hi, accS[i][j]);
                }
            }
        }
        float s[4][4];
#pragma unroll
        for (int i = 0; i < 4; i++)
#pragma unroll
            for (int j = 0; j < 4; j++) {
                float2 f = unpack2(accS[i][j]);
                s[i][j] = f.x + f.y;
            }
        if (kb == qt) {   // diagonal block: per-element causal mask
#pragma unroll
            for (int i = 0; i < 4; i++)
#pragma unroll
                for (int j = 0; j < 4; j++)
                    if (kgs + 16 * j > qgs + 16 * i) s[i][j] = -1.0e30f;
        }

        // ---- fixed-max softmax: p = exp2(s); partial l in registers ----
#pragma unroll
        for (int i = 0; i < 4; i++) {
            const int row = qgs + 16 * i;
#pragma unroll
            for (int j = 0; j < 4; j++) {
                float p = fast_exp2(s[i][j]);
                sS[row * SS_S + kgs + 16 * j] = p;
                lp[i] += p;
            }
        }
        __syncwarp();   // sS written/read within the same 16-lane groups only

        // ---- PV: p via LDS.128 (4 kj at once), v via LDS.128 ----
#pragma unroll 2
        for (int kj4 = 0; kj4 < 16; kj4++) {
            float4 p4[4];
#pragma unroll
            for (int i = 0; i < 4; i++)
                p4[i] = *(const float4*)(sS + (qgs + 16 * i) * SS_S + 4 * kj4);
#pragma unroll
            for (int t = 0; t < 4; t++) {
                const int kj = 4 * kj4 + t;
                U64x2 va = *(const U64x2*)(sV + kj * SV_S + 4 * kgs);
                U64x2 vb = *(const U64x2*)(sV + kj * SV_S + 4 * kgs + 64);
#pragma unroll
                for (int i = 0; i < 4; i++) {
                    float p = (t == 0) ? p4[i].x : (t == 1) ? p4[i].y
                            : (t == 2) ? p4[i].z : p4[i].w;
                    u64 p2 = pack2(p, p);
                    accO[i][0] = ffma2(p2, va.lo, accO[i][0]);
                    accO[i][1] = ffma2(p2, va.hi, accO[i][1]);
                    accO[i][2] = ffma2(p2, vb.lo, accO[i][2]);
                    accO[i][3] = ffma2(p2, vb.hi, accO[i][3]);
                }
            }
        }
    }

    // ---- finalize: reduce l across the 16-lane group once, divide, write ----
#pragma unroll
    for (int i = 0; i < 4; i++) {
        float rs = lp[i];
#pragma unroll
        for (int off = 8; off >= 1; off >>= 1)
            rs += __shfl_xor_sync(0xffffffffu, rs, off);
        float inv = 1.0f / rs;
        u64 inv2 = pack2(inv, inv);
        float* optr = out + (u64)(base + q0 + qgs + 16 * i) * NH;
        *(u64*)(optr + 4 * kgs)      = fmul2(accO[i][0], inv2);
        *(u64*)(optr + 4 * kgs + 2)  = fmul2(accO[i][1], inv2);
        *(u64*)(optr + 4 * kgs + 64) = fmul2(accO[i][2], inv2);
        *(u64*)(optr + 4 * kgs + 66) = fmul2(accO[i][3], inv2);
    }
}

// ============================================================================
extern "C" void kernel_launch(void* const* d_in, const int* in_sizes, int n_in,
                              void* d_out, int out_size) {
    const float* X  = (const float*)d_in[0];
    const float* pm = (const float*)d_in[1];
    const float* Wq = (const float*)d_in[2];
    const float* Wk = (const float*)d_in[3];
    const float* Wv = (const float*)d_in[4];
    float* out = (float*)d_out;

    static bool attr_set = false;   // host-side config, identical every call
    if (!attr_set) {
        cudaFuncSetAttribute(qkv_kernel, cudaFuncAttributeMaxDynamicSharedMemorySize,
                             QKV_SMEM_BYTES);
        cudaFuncSetAttribute(attn_kernel, cudaFuncAttributeMaxDynamicSharedMemorySize,
                             ATTN_SMEM_BYTES);
        attr_set = true;
    }

    qkv_kernel<<<dim3(MROWS / 128, 3, 1), 256, QKV_SMEM_BYTES>>>(X, pm, Wq, Wk, Wv);
    attn_kernel<<<dim3(256, 1, 1), 256, ATTN_SMEM_BYTES>>>(out);
}